// round 4
// baseline (speedup 1.0000x reference)
#include <cuda_runtime.h>
#include <math.h>

// Problem constants (shape-specialized)
#define Bx  64
#define Sx  128
#define Ex  1024
#define Hx  1024
#define Ox  135
#define WLx 64
#define PLx 32
#define WDx 200
#define H3  (3*Hx)
#define GSPLIT 11            // K-split for h@W_hh (partial buffers, no atomics)

// ---------------- scratch (static device globals) --------------------------
__device__ float g_h[2*Bx*Hx];                 // ping-pong hidden state
__device__ float g_WtEd [Ex*Hx];               // [e][j]
__device__ float g_WtAtt[Ex*Hx];               // [e][j]
__device__ float g_WtWatt[WDx*Hx];             // [k][j]
__device__ float g_WtIh [Ox*H3];               // [k][n]
__device__ float g_WtHh [Hx*H3];               // [k][n]
__device__ float g_WtOut[H3*Ox];               // [k][o]
__device__ float g_encp [(size_t)Sx*Bx*Hx];    // [s][b][j]
__device__ float g_wordp[(size_t)WLx*Bx*Hx];   // [w][b][j]
__device__ float g_Ci[Bx*H3];
__device__ float g_ChPart[(size_t)GSPLIT*Bx*H3];
__device__ float g_cat[Bx*H3];                 // [h | ctx | wctx] per b

__device__ __forceinline__ float4 ld4(const float* p) { return *(const float4*)p; }

// ---------------- transposes ------------------------------------------------
__device__ void transpose_one(float* dst, const float* src, int R, int C) {
    __shared__ float t[32][33];
    int c0 = blockIdx.x * 32, r0 = blockIdx.y * 32;
    int x = threadIdx.x, y = threadIdx.y;            // blockDim (32,8)
    #pragma unroll
    for (int i = 0; i < 32; i += 8) {
        int r = r0 + y + i, c = c0 + x;
        t[y + i][x] = (r < R && c < C) ? src[(size_t)r * C + c] : 0.f;
    }
    __syncthreads();
    #pragma unroll
    for (int i = 0; i < 32; i += 8) {
        int r = r0 + x, c = c0 + y + i;
        if (r < R && c < C) dst[(size_t)c * R + r] = t[x][y + i];
    }
}
__global__ void transA_kernel(const float* W_ed, const float* W_att, const float* W_hh) {
    if      (blockIdx.z == 0) transpose_one(g_WtEd,  W_ed,  Hx, Ex);
    else if (blockIdx.z == 1) transpose_one(g_WtAtt, W_att, Hx, Ex);
    else                      transpose_one(g_WtHh,  W_hh,  H3, Hx);
}
__global__ void transB_kernel(const float* W_watt, const float* W_ih, const float* W_out) {
    if      (blockIdx.z == 0) transpose_one(g_WtWatt, W_watt, Hx, WDx);
    else if (blockIdx.z == 1) transpose_one(g_WtIh,   W_ih,   H3, Ox);
    else                      transpose_one(g_WtOut,  W_out,  Ox, H3);
}

// ---------------- generic tiled GEMM core -----------------------------------
// C[M,N] (+)= A[M,Kt] @ Bt[Kt,N]; A is up to 3 row-major K-segments.
struct ASegs { const float* A0; int K0; const float* A1; int K1; const float* A2; int K2; };

__device__ __forceinline__ float aload(const ASegs& A, int m, int k) {
    if (k < A.K0) return A.A0[(size_t)m * A.K0 + k];
    k -= A.K0;
    if (k < A.K1) return A.A1[(size_t)m * A.K1 + k];
    k -= A.K1;
    return A.A2[(size_t)m * A.K2 + k];
}

__device__ void gemm_tile(const ASegs A, int M, const float* Bt, int ldb, int N,
                          const float* bias, float* C, int ldc,
                          int mTile, int nTile, int kBeg, int kEnd, bool atomic)
{
    __shared__ __align__(16) float As[16][68];
    __shared__ __align__(16) float Bs[16][64];
    float acc[4][4];
    #pragma unroll
    for (int i = 0; i < 4; i++)
        #pragma unroll
        for (int j = 0; j < 4; j++) acc[i][j] = 0.f;

    int tid = threadIdx.x;               // 256 threads
    int tx = tid & 15, ty = tid >> 4;

    for (int k0 = kBeg; k0 < kEnd; k0 += 16) {
        #pragma unroll
        for (int u = 0; u < 4; u++) {
            int e = tid + u * 256;
            int m = e >> 4, kk = e & 15;
            int gk = k0 + kk, gm = mTile + m;
            float v = 0.f;
            if (gk < kEnd && gm < M) v = aload(A, gm, gk);
            As[kk][m] = v;
        }
        #pragma unroll
        for (int u = 0; u < 4; u++) {
            int e = tid + u * 256;
            int kk = e >> 6, n = e & 63;
            int gk = k0 + kk, gn = nTile + n;
            float v = 0.f;
            if (gk < kEnd && gn < N) v = Bt[(size_t)gk * ldb + gn];
            Bs[kk][n] = v;
        }
        __syncthreads();
        #pragma unroll
        for (int kk = 0; kk < 16; kk++) {
            float4 a4 = *(const float4*)&As[kk][ty * 4];
            float4 b4 = *(const float4*)&Bs[kk][tx * 4];
            float a[4] = {a4.x, a4.y, a4.z, a4.w};
            float bv[4] = {b4.x, b4.y, b4.z, b4.w};
            #pragma unroll
            for (int i = 0; i < 4; i++)
                #pragma unroll
                for (int j = 0; j < 4; j++)
                    acc[i][j] += a[i] * bv[j];
        }
        __syncthreads();
    }
    #pragma unroll
    for (int i = 0; i < 4; i++) {
        int gm = mTile + ty * 4 + i;
        if (gm >= M) continue;
        #pragma unroll
        for (int j = 0; j < 4; j++) {
            int gn = nTile + tx * 4 + j;
            if (gn >= N) continue;
            float addb = (bias && kBeg == 0) ? bias[gn] : 0.f;
            if (atomic) atomicAdd(&C[(size_t)gm * ldc + gn], acc[i][j] + addb);
            else        C[(size_t)gm * ldc + gn] = acc[i][j] + addb;
        }
    }
}

__global__ void __launch_bounds__(256) gemm_kernel(
    const float* A0, int K0, const float* A1, int K1, const float* A2, int K2,
    const float* Bt, int ldb, int N, const float* bias, float* C, int ldc, int M)
{
    ASegs A{A0, K0, A1, K1, A2, K2};
    int Kt = K0 + K1 + K2;
    int G = gridDim.z;
    int chunk = (Kt + G - 1) / G;
    int kBeg = blockIdx.z * chunk;
    int kEnd = min(Kt, kBeg + chunk);
    gemm_tile(A, M, Bt, ldb, N, bias, C, ldc,
              blockIdx.y * 64, blockIdx.x * 64, kBeg, kEnd, G > 1);
}

// ---------------- fused GRU input+hidden GEMM -------------------------------
// z==0:      g_Ci = x @ W_ihT + b_ih        (+ zero pose_t if given)
// z=1..G:    g_ChPart[z-1] = h @ W_hhT chunk (plain stores, deterministic)
__global__ void __launch_bounds__(256) gru_gemm_kernel(const float* x, const float* b_ih,
                                                       int parity, float* poseZero)
{
    int z = blockIdx.z;
    if (z == 0) {
        if (poseZero) {
            int base = blockIdx.x * 180;
            for (int i = threadIdx.x; i < 180; i += 256) {
                int idx = base + i;
                if (idx < Bx * Ox) poseZero[idx] = 0.f;
            }
        }
        ASegs A{x, Ox, nullptr, 0, nullptr, 0};
        gemm_tile(A, Bx, g_WtIh, H3, H3, b_ih, g_Ci, H3,
                  0, blockIdx.x * 64, 0, Ox, false);
    } else {
        int chunk = (Hx + GSPLIT - 1) / GSPLIT;     // 94
        int kBeg = (z - 1) * chunk, kEnd = min(Hx, kBeg + chunk);
        const float* h = g_h + (size_t)parity * (Bx * Hx);
        ASegs A{h, Hx, nullptr, 0, nullptr, 0};
        gemm_tile(A, Bx, g_WtHh, H3, H3, nullptr,
                  g_ChPart + (size_t)(z - 1) * Bx * H3, H3,
                  0, blockIdx.x * 64, kBeg, kEnd, false);
    }
}

// ---------------- fused gates + dual online-softmax attention ---------------
// mode 0 (warm): 64 blocks, gates only, write h[new].
// mode 1 (decode): 128 blocks; bb<64: gates + enc-attn, writes h[new], cat[h|ctx];
//                  bb>=64: gates (redundant) + word-attn, writes cat[wctx].
__device__ __forceinline__ float gru1(float ir, float iz, float inn,
                                      float hr, float hz, float hn, float h) {
    float r = 1.f / (1.f + __expf(-(ir + hr)));
    float z = 1.f / (1.f + __expf(-(iz + hz)));
    float n = tanhf(inn + r * hn);
    return (1.f - z) * n + z * h;
}

__global__ void __launch_bounds__(256) fused_kernel(const float* __restrict__ b_hh,
                                                    int parity, int mode)
{
    __shared__ float red[8][9];
    __shared__ float sc[8];

    int tid = threadIdx.x;
    int lane = tid & 31, warp = tid >> 5;
    int bb = blockIdx.x;
    int b = bb & 63;
    bool isWord = bb >= 64;

    const float* hOld = g_h + (size_t)parity * (Bx * Hx);
    float*       hNew = g_h + (size_t)(parity ^ 1) * (Bx * Hx);

    int j4 = tid * 4;
    const float* ci = g_Ci + (size_t)b * H3;
    float4 ir  = ld4(ci + j4);
    float4 iz  = ld4(ci + Hx + j4);
    float4 inn = ld4(ci + 2 * Hx + j4);
    float4 hr = ld4(b_hh + j4);
    float4 hz = ld4(b_hh + Hx + j4);
    float4 hn = ld4(b_hh + 2 * Hx + j4);
    #pragma unroll
    for (int g = 0; g < GSPLIT; g++) {
        const float* cp = g_ChPart + ((size_t)g * Bx + b) * H3;
        float4 a = ld4(cp + j4), c2 = ld4(cp + Hx + j4), d = ld4(cp + 2 * Hx + j4);
        hr.x += a.x;  hr.y += a.y;  hr.z += a.z;  hr.w += a.w;
        hz.x += c2.x; hz.y += c2.y; hz.z += c2.z; hz.w += c2.w;
        hn.x += d.x;  hn.y += d.y;  hn.z += d.z;  hn.w += d.w;
    }
    float4 ho = ld4(hOld + (size_t)b * Hx + j4);
    float4 hv;
    hv.x = gru1(ir.x, iz.x, inn.x, hr.x, hz.x, hn.x, ho.x);
    hv.y = gru1(ir.y, iz.y, inn.y, hr.y, hz.y, hn.y, ho.y);
    hv.z = gru1(ir.z, iz.z, inn.z, hr.z, hz.z, hn.z, ho.z);
    hv.w = gru1(ir.w, iz.w, inn.w, hr.w, hz.w, hn.w, ho.w);
    if (bb < 64) *((float4*)(hNew + (size_t)b * Hx + j4)) = hv;
    if (mode == 0) return;

    const float* P = isWord ? g_wordp : g_encp;
    int Slen = isWord ? WLx : Sx;

    float m = -1e30f, l = 0.f;
    float4 acc = make_float4(0.f, 0.f, 0.f, 0.f);

    for (int s0 = 0; s0 < Slen; s0 += 8) {
        float4 ep[8];
        float  pd[8];
        #pragma unroll
        for (int cc = 0; cc < 8; cc++) {
            float4 v = ((const float4*)(P + ((size_t)(s0 + cc) * Bx + b) * Hx))[tid];
            ep[cc] = v;
            pd[cc] = v.x * hv.x + v.y * hv.y + v.z * hv.z + v.w * hv.w;
        }
        #pragma unroll
        for (int cc = 0; cc < 8; cc++) {
            float v = pd[cc];
            v += __shfl_xor_sync(0xffffffffu, v, 16);
            v += __shfl_xor_sync(0xffffffffu, v, 8);
            v += __shfl_xor_sync(0xffffffffu, v, 4);
            v += __shfl_xor_sync(0xffffffffu, v, 2);
            v += __shfl_xor_sync(0xffffffffu, v, 1);
            if (lane == 0) red[warp][cc] = v;
        }
        __syncthreads();
        if (tid < 8) {
            float v = 0.f;
            #pragma unroll
            for (int w = 0; w < 8; w++) v += red[w][tid];
            sc[tid] = v;
        }
        __syncthreads();
        float mx = m;
        #pragma unroll
        for (int cc = 0; cc < 8; cc++) mx = fmaxf(mx, sc[cc]);
        float alpha = __expf(m - mx);
        float p[8]; float ls = 0.f;
        #pragma unroll
        for (int cc = 0; cc < 8; cc++) { p[cc] = __expf(sc[cc] - mx); ls += p[cc]; }
        l = l * alpha + ls;
        float ax = acc.x * alpha, ay = acc.y * alpha, az = acc.z * alpha, aw = acc.w * alpha;
        #pragma unroll
        for (int cc = 0; cc < 8; cc++) {
            ax += p[cc] * ep[cc].x; ay += p[cc] * ep[cc].y;
            az += p[cc] * ep[cc].z; aw += p[cc] * ep[cc].w;
        }
        acc.x = ax; acc.y = ay; acc.z = az; acc.w = aw;
        m = mx;
        __syncthreads();
    }
    float inv = 1.f / l;
    float4 o4 = make_float4(acc.x * inv, acc.y * inv, acc.z * inv, acc.w * inv);
    float* cat = g_cat + (size_t)b * H3;
    if (!isWord) {
        ((float4*)(cat))[tid]            = hv;   // h part
        ((float4*)(cat + Hx))[tid]       = o4;   // ctx
    } else {
        ((float4*)(cat + 2 * Hx))[tid]   = o4;   // wctx
    }
}

// ---------------- host launcher ---------------------------------------------
extern "C" void kernel_launch(void* const* d_in, const int* in_sizes, int n_in,
                              void* d_out, int out_size)
{
    const float* enc_states = (const float*)d_in[0];
    const float* enc_hidden = (const float*)d_in[1];
    const float* prev_poses = (const float*)d_in[2];
    const float* words      = (const float*)d_in[3];
    // d_in[4] = real_poses_len (device scalar) — derive T from out_size instead
    const float* W_ed  = (const float*)d_in[5];
    const float* b_ed  = (const float*)d_in[6];
    const float* W_att = (const float*)d_in[7];
    const float* b_att = (const float*)d_in[8];
    const float* W_watt= (const float*)d_in[9];
    const float* b_watt= (const float*)d_in[10];
    const float* W_ih  = (const float*)d_in[11];
    const float* W_hh  = (const float*)d_in[12];
    const float* b_ih  = (const float*)d_in[13];
    const float* b_hh  = (const float*)d_in[14];
    const float* W_out = (const float*)d_in[15];
    const float* b_out = (const float*)d_in[16];
    float* out = (float*)d_out;
    int T = out_size / (Bx * Ox);
    if (T < 1) T = 1;

    float *pWtEd, *pWtAtt, *pWtWatt, *pWtOut, *pH, *pEncp, *pWordp, *pCat;
    cudaGetSymbolAddress((void**)&pWtEd,  g_WtEd);
    cudaGetSymbolAddress((void**)&pWtAtt, g_WtAtt);
    cudaGetSymbolAddress((void**)&pWtWatt,g_WtWatt);
    cudaGetSymbolAddress((void**)&pWtOut, g_WtOut);
    cudaGetSymbolAddress((void**)&pH,     g_h);
    cudaGetSymbolAddress((void**)&pEncp,  g_encp);
    cudaGetSymbolAddress((void**)&pWordp, g_wordp);
    cudaGetSymbolAddress((void**)&pCat,   g_cat);

    dim3 tb(32, 8);
    // Launch order chosen so ncu (-s 5 -c 1) profiles the 6th launch = gru_gemm.
    transA_kernel<<<dim3(32, 96, 3), tb>>>(W_ed, W_att, W_hh);          // 1
    transB_kernel<<<dim3(96, 96, 3), tb>>>(W_watt, W_ih, W_out);        // 2
    // h0 = [eh0 | eh1] @ W_edT + b_ed  -> g_h buffer 0
    gemm_kernel<<<dim3(16, 1, 1), 256>>>(enc_hidden, Ex/2,              // 3
                                         enc_hidden + (size_t)Bx*(Ex/2), Ex/2,
                                         nullptr, 0,
                                         pWtEd, Hx, Hx, b_ed, pH, Hx, Bx);
    gemm_kernel<<<dim3(16, 128, 1), 256>>>(enc_states, Ex, nullptr, 0, nullptr, 0,  // 4
                                           pWtAtt, Hx, Hx, b_att, pEncp, Hx, Sx*Bx);
    gemm_kernel<<<dim3(16, 64, 1), 256>>>(words, WDx, nullptr, 0, nullptr, 0,       // 5
                                          pWtWatt, Hx, Hx, b_watt, pWordp, Hx, WLx*Bx);

    // Warm-up scan (step s reads g_h[s&1], writes g_h[(s&1)^1]; h0 is in buffer 0)
    for (int t = 0; t < PLx; t++) {
        int p = t & 1;
        gru_gemm_kernel<<<dim3(48, 1, GSPLIT + 1), 256>>>(prev_poses + (size_t)t*Bx*Ox,
                                                          b_ih, p, nullptr);  // t=0 is launch 6 (profiled)
        fused_kernel<<<64, 256>>>(b_hh, p, 0);
    }

    // Decode loop (global step 32+t -> parity t&1)
    for (int t = 0; t < T; t++) {
        int p = t & 1;
        const float* x = (t == 0) ? prev_poses + (size_t)(PLx - 1)*Bx*Ox
                                  : out + (size_t)(t - 1)*Bx*Ox;
        float* pose_t = out + (size_t)t*Bx*Ox;
        gru_gemm_kernel<<<dim3(48, 1, GSPLIT + 1), 256>>>(x, b_ih, p, pose_t);
        fused_kernel<<<128, 256>>>(b_hh, p, 1);
        // pose_t += [h|ctx|wctx] @ W_outT  (split-K=12, atomics; b_out added by z==0)
        gemm_kernel<<<dim3(3, 1, 12), 256>>>(pCat, H3, nullptr, 0, nullptr, 0,
                                             pWtOut, Ox, Ox, b_out, pose_t, Ox, Bx);
    }
}

// round 5
// speedup vs baseline: 2.2856x; 2.2856x over previous
#include <cuda_runtime.h>
#include <math.h>

// Problem constants (shape-specialized)
#define Bx  64
#define Sx  128
#define Ex  1024
#define Hx  1024
#define Ox  135
#define WLx 64
#define PLx 32
#define WDx 200
#define H3  (3*Hx)
#define GS  8               // K-split count for h@W_hh (atomic accumulation)

// ---------------- scratch (static device globals) --------------------------
__device__ float g_h[2*Bx*Hx];                 // ping-pong hidden state
__device__ float g_Ch[2*Bx*H3];                // ping-pong gh accumulator (b_hh-seeded)
__device__ float g_WtEd [Ex*Hx];
__device__ float g_WtAtt[Ex*Hx];
__device__ float g_WtWatt[WDx*Hx];
__device__ float g_WtIh [Ox*H3];
__device__ float g_WtHh [Hx*H3];
__device__ float g_WtOut[H3*Ox];
__device__ float g_encp [(size_t)Sx*Bx*Hx];    // [s][b][j]
__device__ float g_wordp[(size_t)WLx*Bx*Hx];   // [w][b][j]
__device__ float g_Ci[Bx*H3];
__device__ float g_cat[Bx*H3];                 // [h | ctx | wctx] per b

__device__ __forceinline__ float4 ld4(const float* p) { return *(const float4*)p; }

// ---------------- transposes ------------------------------------------------
__device__ void transpose_one(float* dst, const float* src, int R, int C) {
    __shared__ float t[32][33];
    int c0 = blockIdx.x * 32, r0 = blockIdx.y * 32;
    int x = threadIdx.x, y = threadIdx.y;            // blockDim (32,8)
    #pragma unroll
    for (int i = 0; i < 32; i += 8) {
        int r = r0 + y + i, c = c0 + x;
        t[y + i][x] = (r < R && c < C) ? src[(size_t)r * C + c] : 0.f;
    }
    __syncthreads();
    #pragma unroll
    for (int i = 0; i < 32; i += 8) {
        int r = r0 + x, c = c0 + y + i;
        if (r < R && c < C) dst[(size_t)c * R + r] = t[x][y + i];
    }
}
__global__ void transA_kernel(const float* W_ed, const float* W_att, const float* W_hh) {
    if      (blockIdx.z == 0) transpose_one(g_WtEd,  W_ed,  Hx, Ex);
    else if (blockIdx.z == 1) transpose_one(g_WtAtt, W_att, Hx, Ex);
    else                      transpose_one(g_WtHh,  W_hh,  H3, Hx);
}
__global__ void transB_kernel(const float* W_watt, const float* W_ih, const float* W_out) {
    if      (blockIdx.z == 0) transpose_one(g_WtWatt, W_watt, Hx, WDx);
    else if (blockIdx.z == 1) transpose_one(g_WtIh,   W_ih,   H3, Ox);
    else                      transpose_one(g_WtOut,  W_out,  Ox, H3);
}

__global__ void initCh_kernel(const float* b_hh) {   // seed Ch[0] = b_hh
    int i = blockIdx.x * 256 + threadIdx.x;
    if (i < Bx * H3) g_Ch[i] = b_hh[i % H3];
}

// ---------------- generic tiled GEMM core -----------------------------------
struct ASegs { const float* A0; int K0; const float* A1; int K1; const float* A2; int K2; };

__device__ __forceinline__ float aload(const ASegs& A, int m, int k) {
    if (k < A.K0) return A.A0[(size_t)m * A.K0 + k];
    k -= A.K0;
    if (k < A.K1) return A.A1[(size_t)m * A.K1 + k];
    k -= A.K1;
    return A.A2[(size_t)m * A.K2 + k];
}

__device__ void gemm_tile(const ASegs A, int M, const float* Bt, int ldb, int N,
                          const float* bias, float* C, int ldc,
                          int mTile, int nTile, int kBeg, int kEnd, bool atomic)
{
    __shared__ __align__(16) float As[16][68];
    __shared__ __align__(16) float Bs[16][64];
    float acc[4][4];
    #pragma unroll
    for (int i = 0; i < 4; i++)
        #pragma unroll
        for (int j = 0; j < 4; j++) acc[i][j] = 0.f;

    int tid = threadIdx.x;               // 256 threads
    int tx = tid & 15, ty = tid >> 4;

    for (int k0 = kBeg; k0 < kEnd; k0 += 16) {
        #pragma unroll
        for (int u = 0; u < 4; u++) {
            int e = tid + u * 256;
            int m = e >> 4, kk = e & 15;
            int gk = k0 + kk, gm = mTile + m;
            float v = 0.f;
            if (gk < kEnd && gm < M) v = aload(A, gm, gk);
            As[kk][m] = v;
        }
        #pragma unroll
        for (int u = 0; u < 4; u++) {
            int e = tid + u * 256;
            int kk = e >> 6, n = e & 63;
            int gk = k0 + kk, gn = nTile + n;
            float v = 0.f;
            if (gk < kEnd && gn < N) v = Bt[(size_t)gk * ldb + gn];
            Bs[kk][n] = v;
        }
        __syncthreads();
        #pragma unroll
        for (int kk = 0; kk < 16; kk++) {
            float4 a4 = *(const float4*)&As[kk][ty * 4];
            float4 b4 = *(const float4*)&Bs[kk][tx * 4];
            float a[4] = {a4.x, a4.y, a4.z, a4.w};
            float bv[4] = {b4.x, b4.y, b4.z, b4.w};
            #pragma unroll
            for (int i = 0; i < 4; i++)
                #pragma unroll
                for (int j = 0; j < 4; j++)
                    acc[i][j] += a[i] * bv[j];
        }
        __syncthreads();
    }
    #pragma unroll
    for (int i = 0; i < 4; i++) {
        int gm = mTile + ty * 4 + i;
        if (gm >= M) continue;
        #pragma unroll
        for (int j = 0; j < 4; j++) {
            int gn = nTile + tx * 4 + j;
            if (gn >= N) continue;
            float addb = (bias && kBeg == 0) ? bias[gn] : 0.f;
            if (atomic) atomicAdd(&C[(size_t)gm * ldc + gn], acc[i][j] + addb);
            else        C[(size_t)gm * ldc + gn] = acc[i][j] + addb;
        }
    }
}

__global__ void __launch_bounds__(256) gemm_kernel(
    const float* A0, int K0, const float* A1, int K1, const float* A2, int K2,
    const float* Bt, int ldb, int N, const float* bias, float* C, int ldc, int M)
{
    ASegs A{A0, K0, A1, K1, A2, K2};
    int Kt = K0 + K1 + K2;
    int G = gridDim.z;
    int chunk = (Kt + G - 1) / G;
    int kBeg = blockIdx.z * chunk;
    int kEnd = min(Kt, kBeg + chunk);
    gemm_tile(A, M, Bt, ldb, N, bias, C, ldc,
              blockIdx.y * 64, blockIdx.x * 64, kBeg, kEnd, G > 1);
}

// ---------------- fused GRU input+hidden GEMM -------------------------------
// z==0:      g_Ci = x @ W_ihT + b_ih   (+ zero pose_t if given)
// z=1..GS:   g_Ch[parity] += h @ W_hhT chunk (atomic; buffer pre-seeded with b_hh)
__global__ void __launch_bounds__(256) gru_gemm_kernel(const float* x, const float* b_ih,
                                                       int parity, float* poseZero)
{
    int z = blockIdx.z;
    if (z == 0) {
        if (poseZero) {
            int base = blockIdx.x * 180;
            for (int i = threadIdx.x; i < 180; i += 256) {
                int idx = base + i;
                if (idx < Bx * Ox) poseZero[idx] = 0.f;
            }
        }
        ASegs A{x, Ox, nullptr, 0, nullptr, 0};
        gemm_tile(A, Bx, g_WtIh, H3, H3, b_ih, g_Ci, H3,
                  0, blockIdx.x * 64, 0, Ox, false);
    } else {
        int chunk = Hx / GS;                       // 128
        int kBeg = (z - 1) * chunk, kEnd = kBeg + chunk;
        const float* h = g_h + (size_t)parity * (Bx * Hx);
        ASegs A{h, Hx, nullptr, 0, nullptr, 0};
        gemm_tile(A, Bx, g_WtHh, H3, H3, nullptr,
                  g_Ch + (size_t)parity * (Bx * H3), H3,
                  0, blockIdx.x * 64, kBeg, kEnd, true);
    }
}

// ---------------- fused gates + dual attention (warp-per-row) ---------------
__device__ __forceinline__ float gru1(float ir, float iz, float inn,
                                      float hr, float hz, float hn, float h) {
    float r = 1.f / (1.f + __expf(-(ir + hr)));
    float z = 1.f / (1.f + __expf(-(iz + hz)));
    float n = tanhf(inn + r * hn);
    return (1.f - z) * n + z * h;
}
__device__ __forceinline__ float wredsum(float v) {
    v += __shfl_xor_sync(0xffffffffu, v, 16);
    v += __shfl_xor_sync(0xffffffffu, v, 8);
    v += __shfl_xor_sync(0xffffffffu, v, 4);
    v += __shfl_xor_sync(0xffffffffu, v, 2);
    v += __shfl_xor_sync(0xffffffffu, v, 1);
    return v;
}

// mode 0 (warm): 64 blocks — gates only, write h[new], reseed Ch[parity^1].
// mode 1 (decode): 128 blocks; bb<64: gates + enc-attn (+ h write, Ch reseed,
//   cat[h|ctx]); bb>=64: gates redundantly + word-attn -> cat[wctx].
__global__ void __launch_bounds__(256) fused_kernel(const float* __restrict__ b_hh,
                                                    int parity, int mode)
{
    __shared__ __align__(16) float h_s[Hx];
    __shared__ float4 wacc[8][256];     // 32 KB cross-warp partial ctx
    __shared__ float wm[8], wl[8];

    int tid = threadIdx.x;
    int lane = tid & 31, warp = tid >> 5;
    int bb = blockIdx.x;
    int b = bb & 63;
    bool isWord = bb >= 64;

    const float* hOld = g_h + (size_t)parity * (Bx * Hx);
    float*       hNew = g_h + (size_t)(parity ^ 1) * (Bx * Hx);
    const float* Ch   = g_Ch + (size_t)parity * (Bx * H3);
    float*       ChNx = g_Ch + (size_t)(parity ^ 1) * (Bx * H3);

    // ---- gates ----
    int j4 = tid * 4;
    const float* ci = g_Ci + (size_t)b * H3;
    const float* ch = Ch + (size_t)b * H3;
    float4 ir  = ld4(ci + j4);
    float4 iz  = ld4(ci + Hx + j4);
    float4 inn = ld4(ci + 2 * Hx + j4);
    float4 hr  = ld4(ch + j4);
    float4 hz  = ld4(ch + Hx + j4);
    float4 hn  = ld4(ch + 2 * Hx + j4);
    float4 ho  = ld4(hOld + (size_t)b * Hx + j4);
    float4 hv;
    hv.x = gru1(ir.x, iz.x, inn.x, hr.x, hz.x, hn.x, ho.x);
    hv.y = gru1(ir.y, iz.y, inn.y, hr.y, hz.y, hn.y, ho.y);
    hv.z = gru1(ir.z, iz.z, inn.z, hr.z, hz.z, hn.z, ho.z);
    hv.w = gru1(ir.w, iz.w, inn.w, hr.w, hz.w, hn.w, ho.w);

    if (bb < 64) {
        *((float4*)(hNew + (size_t)b * Hx + j4)) = hv;
        // reseed the other parity's gh accumulator with b_hh for step t+1
        float* cn = ChNx + (size_t)b * H3;
        *((float4*)(cn + j4))          = ld4(b_hh + j4);
        *((float4*)(cn + Hx + j4))     = ld4(b_hh + Hx + j4);
        *((float4*)(cn + 2 * Hx + j4)) = ld4(b_hh + 2 * Hx + j4);
    }
    if (mode == 0) return;

    // ---- stage h for attention (lane-major dim access) ----
    ((float4*)h_s)[tid] = hv;
    __syncthreads();

    const float* P = isWord ? g_wordp : g_encp;
    int rowsPerWarp = (isWord ? WLx : Sx) / 8;

    float4 hreg[8];
    #pragma unroll
    for (int k = 0; k < 8; k++) hreg[k] = ((const float4*)h_s)[lane + 32 * k];

    float m = -1e30f, l = 0.f;
    float4 acc[8];
    #pragma unroll
    for (int k = 0; k < 8; k++) acc[k] = make_float4(0.f, 0.f, 0.f, 0.f);

    for (int r = 0; r < rowsPerWarp; r++) {
        int s = warp + 8 * r;
        const float4* row = (const float4*)(P + ((size_t)s * Bx + b) * Hx);
        float4 e[8];
        float d = 0.f;
        #pragma unroll
        for (int k = 0; k < 8; k++) {
            float4 v = row[lane + 32 * k];
            e[k] = v;
            d += v.x * hreg[k].x + v.y * hreg[k].y + v.z * hreg[k].z + v.w * hreg[k].w;
        }
        d = wredsum(d);                       // broadcast to all lanes
        float mx = fmaxf(m, d);
        float alpha = __expf(m - mx);
        float p = __expf(d - mx);
        l = l * alpha + p;
        #pragma unroll
        for (int k = 0; k < 8; k++) {
            acc[k].x = acc[k].x * alpha + p * e[k].x;
            acc[k].y = acc[k].y * alpha + p * e[k].y;
            acc[k].z = acc[k].z * alpha + p * e[k].z;
            acc[k].w = acc[k].w * alpha + p * e[k].w;
        }
        m = mx;
    }

    // ---- cross-warp online-softmax merge ----
    if (lane == 0) { wm[warp] = m; wl[warp] = l; }
    #pragma unroll
    for (int k = 0; k < 8; k++) wacc[warp][lane + 32 * k] = acc[k];
    __syncthreads();

    float M = -1e30f;
    #pragma unroll
    for (int w = 0; w < 8; w++) M = fmaxf(M, wm[w]);
    float L = 0.f;
    #pragma unroll
    for (int w = 0; w < 8; w++) L += __expf(wm[w] - M) * wl[w];
    float4 o = make_float4(0.f, 0.f, 0.f, 0.f);
    #pragma unroll
    for (int w = 0; w < 8; w++) {
        float sc = __expf(wm[w] - M);
        float4 v = wacc[w][tid];
        o.x += sc * v.x; o.y += sc * v.y; o.z += sc * v.z; o.w += sc * v.w;
    }
    float inv = 1.f / L;
    o.x *= inv; o.y *= inv; o.z *= inv; o.w *= inv;

    float* cat = g_cat + (size_t)b * H3;
    if (!isWord) {
        ((float4*)(cat))[tid]      = hv;       // h part
        ((float4*)(cat + Hx))[tid] = o;        // ctx
    } else {
        ((float4*)(cat + 2 * Hx))[tid] = o;    // wctx
    }
}

// ---------------- host launcher ---------------------------------------------
extern "C" void kernel_launch(void* const* d_in, const int* in_sizes, int n_in,
                              void* d_out, int out_size)
{
    const float* enc_states = (const float*)d_in[0];
    const float* enc_hidden = (const float*)d_in[1];
    const float* prev_poses = (const float*)d_in[2];
    const float* words      = (const float*)d_in[3];
    // d_in[4] = real_poses_len (device scalar) — derive T from out_size
    const float* W_ed  = (const float*)d_in[5];
    const float* b_ed  = (const float*)d_in[6];
    const float* W_att = (const float*)d_in[7];
    const float* b_att = (const float*)d_in[8];
    const float* W_watt= (const float*)d_in[9];
    const float* b_watt= (const float*)d_in[10];
    const float* W_ih  = (const float*)d_in[11];
    const float* W_hh  = (const float*)d_in[12];
    const float* b_ih  = (const float*)d_in[13];
    const float* b_hh  = (const float*)d_in[14];
    const float* W_out = (const float*)d_in[15];
    const float* b_out = (const float*)d_in[16];
    float* out = (float*)d_out;
    int T = out_size / (Bx * Ox);
    if (T < 1) T = 1;

    float *pWtEd, *pWtAtt, *pWtWatt, *pWtOut, *pH, *pEncp, *pWordp, *pCat;
    cudaGetSymbolAddress((void**)&pWtEd,  g_WtEd);
    cudaGetSymbolAddress((void**)&pWtAtt, g_WtAtt);
    cudaGetSymbolAddress((void**)&pWtWatt,g_WtWatt);
    cudaGetSymbolAddress((void**)&pWtOut, g_WtOut);
    cudaGetSymbolAddress((void**)&pH,     g_h);
    cudaGetSymbolAddress((void**)&pEncp,  g_encp);
    cudaGetSymbolAddress((void**)&pWordp, g_wordp);
    cudaGetSymbolAddress((void**)&pCat,   g_cat);

    dim3 tb(32, 8);
    initCh_kernel<<<(Bx*H3 + 255)/256, 256>>>(b_hh);                    // 0
    transA_kernel<<<dim3(32, 96, 3), tb>>>(W_ed, W_att, W_hh);          // 1
    transB_kernel<<<dim3(96, 96, 3), tb>>>(W_watt, W_ih, W_out);        // 2
    // h0 = [eh0 | eh1] @ W_edT + b_ed  -> g_h buffer 0
    gemm_kernel<<<dim3(16, 1, 1), 256>>>(enc_hidden, Ex/2,              // 3
                                         enc_hidden + (size_t)Bx*(Ex/2), Ex/2,
                                         nullptr, 0,
                                         pWtEd, Hx, Hx, b_ed, pH, Hx, Bx);

    // Warm-up scan (hot kernels early so ncu -s 5 lands on them)
    for (int t = 0; t < PLx; t++) {
        int p = t & 1;
        gru_gemm_kernel<<<dim3(48, 1, GS + 1), 256>>>(prev_poses + (size_t)t*Bx*Ox,
                                                      b_ih, p, nullptr);
        fused_kernel<<<64, 256>>>(b_hh, p, 0);
    }

    // Attention projections (only needed by decode)
    gemm_kernel<<<dim3(16, 128, 1), 256>>>(enc_states, Ex, nullptr, 0, nullptr, 0,
                                           pWtAtt, Hx, Hx, b_att, pEncp, Hx, Sx*Bx);
    gemm_kernel<<<dim3(16, 64, 1), 256>>>(words, WDx, nullptr, 0, nullptr, 0,
                                          pWtWatt, Hx, Hx, b_watt, pWordp, Hx, WLx*Bx);

    // Decode loop (global step 32+t -> parity t&1; 32 is even so h/Ch parity chains)
    for (int t = 0; t < T; t++) {
        int p = t & 1;
        const float* x = (t == 0) ? prev_poses + (size_t)(PLx - 1)*Bx*Ox
                                  : out + (size_t)(t - 1)*Bx*Ox;
        float* pose_t = out + (size_t)t*Bx*Ox;
        gru_gemm_kernel<<<dim3(48, 1, GS + 1), 256>>>(x, b_ih, p, pose_t);
        fused_kernel<<<128, 256>>>(b_hh, p, 1);
        // pose_t += [h|ctx|wctx] @ W_outT  (split-K=48, atomics; b_out at kBeg==0)
        gemm_kernel<<<dim3(3, 1, 48), 256>>>(pCat, H3, nullptr, 0, nullptr, 0,
                                             pWtOut, Ox, Ox, b_out, pose_t, Ox, Bx);
    }
}